// round 7
// baseline (speedup 1.0000x reference)
#include <cuda_runtime.h>

typedef unsigned long long u64;

// ---------------- f32x2 packed-math helpers (sm_103a) ----------------
__device__ __forceinline__ u64 f2fma(u64 a, u64 b, u64 c) {
    u64 d;
    asm("fma.rn.f32x2 %0, %1, %2, %3;" : "=l"(d) : "l"(a), "l"(b), "l"(c));
    return d;
}
__device__ __forceinline__ u64 f2mul(u64 a, u64 b) {
    u64 d;
    asm("mul.rn.f32x2 %0, %1, %2;" : "=l"(d) : "l"(a), "l"(b));
    return d;
}
__device__ __forceinline__ u64 fpack(float x, float y) {
    u64 d;
    asm("mov.b64 %0, {%1, %2};" : "=l"(d) : "f"(x), "f"(y));
    return d;
}
__device__ __forceinline__ float2 funpack(u64 a) {
    float2 r;
    asm("mov.b64 {%0, %1}, %2;" : "=f"(r.x), "=f"(r.y) : "l"(a));
    return r;
}

// ---------------- problem constants ----------------
#define NN     50000
#define KC     128
#define PC     256
#define BN     8
#define NT     512
#define NI     4
#define EPSV   1e-6f

// smem layout (float offsets)
#define OFF_RES 0          // [8][9][128]  residual        9216
#define OFF_H   9216       // [8][9][128]  normed h        9216
#define OFF_HC  18432      // [8][9][256]  hc / tp         18432
#define OFF_U   36864      // [45][9] scalar sym U         405
#define OFF_G   37312      // [4][3][128]  gamma           1536
#define SMEM_FLOATS 38848

// ---------------- linear_in: h[9][K] @ Win[K][2K] -> hc[9][2K] ----------------
// Thread = (pg 0..63) x (node b 0..7); owns 4 p-cols: pg + 64j.
// k-parity f32x2 accumulators; h read as natural float4 broadcast (1 per m per k-quad);
// weights: 4 LDG.32 + 2 fpack per p-col per k-quad, amortized over ML FMAs.
template<int ML, int M0>
__device__ __forceinline__ void lin_in(const float* __restrict__ W,
                                       const float* __restrict__ s_h,
                                       float* __restrict__ s_hc,
                                       int pg, int b)
{
    u64 acc[4][ML];
    #pragma unroll
    for (int j = 0; j < 4; j++)
        #pragma unroll
        for (int m = 0; m < ML; m++) acc[j][m] = 0ull;

    const float* hbase = s_h + (b * 9 + M0) * 128;

    #pragma unroll 2
    for (int k = 0; k < KC; k += 4) {
        u64 w0[4], w1[4];
        #pragma unroll
        for (int j = 0; j < 4; j++) {
            const float* wp = W + (size_t)k * PC + pg + 64 * j;
            w0[j] = fpack(wp[0],      wp[PC]);
            w1[j] = fpack(wp[2 * PC], wp[3 * PC]);
        }
        #pragma unroll
        for (int m = 0; m < ML; m++) {
            const ulonglong2 h2 = *(const ulonglong2*)(hbase + m * 128 + k);
            #pragma unroll
            for (int j = 0; j < 4; j++) {
                acc[j][m] = f2fma(h2.x, w0[j], acc[j][m]);
                acc[j][m] = f2fma(h2.y, w1[j], acc[j][m]);
            }
        }
    }
    #pragma unroll
    for (int m = 0; m < ML; m++)
        #pragma unroll
        for (int j = 0; j < 4; j++) {
            float2 v = funpack(acc[j][m]);
            s_hc[(b * 9 + M0 + m) * 256 + pg + 64 * j] = v.x + v.y;
        }
}

// ---------------- linear_out: tp[9][2K] @ Wout[2K][K] + skip ----------------
// Thread = (cq 0..31) x (node bg) x (m-half); owns col-pairs cq and cq+32.
// hv float4 broadcast + fpack reused across both col-pairs -> 8 FMAs per LDS.128.
template<int ML, int M0>
__device__ __forceinline__ void lin_out(const float* __restrict__ W,
                                        const float* __restrict__ s_hc,
                                        float* __restrict__ s_res,
                                        int cq, int bg)
{
    u64 acc0[ML], acc1[ML];
    #pragma unroll
    for (int m = 0; m < ML; m++) { acc0[m] = 0ull; acc1[m] = 0ull; }

    const float* wA = W + 2 * cq;
    const float* wB = W + 2 * (cq + 32);

    #pragma unroll 2
    for (int p = 0; p < PC; p += 4) {
        u64 wA0 = *(const u64*)(wA + (size_t)(p + 0) * KC);
        u64 wA1 = *(const u64*)(wA + (size_t)(p + 1) * KC);
        u64 wA2 = *(const u64*)(wA + (size_t)(p + 2) * KC);
        u64 wA3 = *(const u64*)(wA + (size_t)(p + 3) * KC);
        u64 wB0 = *(const u64*)(wB + (size_t)(p + 0) * KC);
        u64 wB1 = *(const u64*)(wB + (size_t)(p + 1) * KC);
        u64 wB2 = *(const u64*)(wB + (size_t)(p + 2) * KC);
        u64 wB3 = *(const u64*)(wB + (size_t)(p + 3) * KC);
        #pragma unroll
        for (int m = 0; m < ML; m++) {
            const float4 hv = *(const float4*)
                (s_hc + (bg * 9 + M0 + m) * 256 + p);
            u64 hx = fpack(hv.x, hv.x);
            u64 hy = fpack(hv.y, hv.y);
            u64 hz = fpack(hv.z, hv.z);
            u64 hw = fpack(hv.w, hv.w);
            acc0[m] = f2fma(hx, wA0, acc0[m]);
            acc0[m] = f2fma(hy, wA1, acc0[m]);
            acc0[m] = f2fma(hz, wA2, acc0[m]);
            acc0[m] = f2fma(hw, wA3, acc0[m]);
            acc1[m] = f2fma(hx, wB0, acc1[m]);
            acc1[m] = f2fma(hy, wB1, acc1[m]);
            acc1[m] = f2fma(hz, wB2, acc1[m]);
            acc1[m] = f2fma(hw, wB3, acc1[m]);
        }
    }
    #pragma unroll
    for (int m = 0; m < ML; m++) {
        float* r0 = s_res + (bg * 9 + M0 + m) * 128 + 2 * cq;
        float* r1 = r0 + 64;
        float2 a = funpack(acc0[m]);
        float2 bb = funpack(acc1[m]);
        float2 v0 = *(float2*)r0;
        float2 v1 = *(float2*)r1;
        v0.x += a.x;  v0.y += a.y;
        v1.x += bb.x; v1.y += bb.y;
        *(float2*)r0 = v0;
        *(float2*)r1 = v1;
    }
}

// ---------------- fused 4-iteration kernel, 8 nodes per CTA, 512 threads ----------------
__global__ void __launch_bounds__(NT, 1)
cg_kernel(const float* __restrict__ f0, const float* __restrict__ f1,
          const float* __restrict__ f2, const float* __restrict__ U,
          const float* __restrict__ gamma, const float* __restrict__ Win,
          const float* __restrict__ Wout, float* __restrict__ out)
{
    extern __shared__ float sm[];
    float* s_res = sm + OFF_RES;
    float* s_h   = sm + OFF_H;
    float* s_hc  = sm + OFF_HC;
    float* s_U   = sm + OFF_U;
    float* s_g   = sm + OFF_G;

    const int tid = threadIdx.x;
    const int n0  = blockIdx.x * BN;

    // --- load features: s_res[b][m][k], m packed [f0 | f1(3) | f2(5)] ---
    {
        float4* dst = (float4*)s_res;
        for (int idx = tid; idx < BN * 9 * 32; idx += NT) {
            int b   = idx / 288;
            int rem = idx - b * 288;
            int m   = rem >> 5;
            int q   = rem & 31;
            int n   = n0 + b;
            const float* src;
            if (m == 0)      src = f0 + (size_t)n * 128;
            else if (m < 4)  src = f1 + (size_t)n * 384 + (m - 1) * 128;
            else             src = f2 + (size_t)n * 640 + (m - 4) * 128;
            dst[idx] = ((const float4*)src)[q];
        }
    }
    // --- symmetrize U into scalar pair layout s_U[pair][c] ---
    for (int tt = tid; tt < 45 * 9; tt += NT) {
        int pair = tt / 9, c = tt - pair * 9;
        int a = 0, rem = pair;
        while (rem > 8 - a) { rem -= 9 - a; a++; }
        int bb = a + rem;
        float u = U[(a * 9 + bb) * 9 + c];
        if (a != bb) u += U[(bb * 9 + a) * 9 + c];
        s_U[pair * 9 + c] = u;
    }
    for (int tt = tid; tt < NI * 3 * KC; tt += NT) s_g[tt] = gamma[tt];
    __syncthreads();

    #pragma unroll 1
    for (int it = 0; it < NI; it++) {
        // ---------- EquivariantRMSNorm -> natural h[b][m][k] ----------
        for (int idx = tid; idx < BN * KC; idx += NT) {
            int b = idx >> 7, k = idx & 127;
            const float* r = s_res + b * 1152 + k;
            float x0 = r[0];
            float x1 = r[128], x2 = r[256],  x3 = r[384];
            float x4 = r[512], x5 = r[640],  x6 = r[768], x7 = r[896], x8 = r[1024];
            float i0 = rsqrtf(x0 * x0 + EPSV);
            float i1 = rsqrtf((x1*x1 + x2*x2 + x3*x3) * (1.0f/3.0f) + EPSV);
            float i2 = rsqrtf((x4*x4 + x5*x5 + x6*x6 + x7*x7 + x8*x8) * 0.2f + EPSV);
            float g0 = s_g[(it * 3 + 0) * 128 + k];
            float g1 = s_g[(it * 3 + 1) * 128 + k];
            float g2 = s_g[(it * 3 + 2) * 128 + k];
            float* h = s_h + b * 1152 + k;
            h[0]    = x0 * i0 * g0;
            h[128]  = x1 * i1 * g1;
            h[256]  = x2 * i1 * g1;
            h[384]  = x3 * i1 * g1;
            h[512]  = x4 * i2 * g2;
            h[640]  = x5 * i2 * g2;
            h[768]  = x6 * i2 * g2;
            h[896]  = x7 * i2 * g2;
            h[1024] = x8 * i2 * g2;
        }
        __syncthreads();

        // ---------- linear_in (K -> 2K), 4 p-cols per thread ----------
        {
            const int pg = tid & 63;
            const int b  = tid >> 6;
            const float* Wi = Win + (size_t)(it * 3) * KC * PC;
            lin_in<1, 0>(Wi + 0 * KC * PC, s_h, s_hc, pg, b);
            lin_in<3, 1>(Wi + 1 * KC * PC, s_h, s_hc, pg, b);
            lin_in<5, 4>(Wi + 2 * KC * PC, s_h, s_hc, pg, b);
        }
        __syncthreads();

        // ---------- CG tensor product, register-preloaded, in-place on s_hc ----------
        {
            const int p2 = tid & 127;
            const int bq = (tid >> 7) * 2;
            float* base0 = s_hc + bq * 2304 + 2 * p2;
            float* base1 = base0 + 2304;
            u64 v0[9], v1[9];
            #pragma unroll
            for (int a = 0; a < 9; a++) {
                v0[a] = *(const u64*)(base0 + a * 256);
                v1[a] = *(const u64*)(base1 + a * 256);
            }
            u64 acc0[9], acc1[9];
            #pragma unroll
            for (int c = 0; c < 9; c++) { acc0[c] = 0ull; acc1[c] = 0ull; }
            int pair = 0;
            #pragma unroll 1
            for (int a = 0; a < 9; a++) {
                #pragma unroll 1
                for (int bb = a; bb < 9; bb++) {
                    u64 pr0 = f2mul(v0[a], v0[bb]);
                    u64 pr1 = f2mul(v1[a], v1[bb]);
                    const float* u = s_U + pair * 9;
                    #pragma unroll
                    for (int c = 0; c < 9; c++) {
                        float us = u[c];
                        u64 uc = fpack(us, us);
                        acc0[c] = f2fma(pr0, uc, acc0[c]);
                        acc1[c] = f2fma(pr1, uc, acc1[c]);
                    }
                    pair++;
                }
            }
            #pragma unroll
            for (int c = 0; c < 9; c++) {
                *(u64*)(base0 + c * 256) = acc0[c];
                *(u64*)(base1 + c * 256) = acc1[c];
            }
        }
        __syncthreads();

        // ---------- linear_out (2K -> K) + skip, split m over 2 thread halves ----------
        {
            const int cq = tid & 31;
            const int bg = (tid >> 5) & 7;
            const int mh = tid >> 8;
            const float* Wo = Wout + (size_t)(it * 3) * PC * KC;
            if (mh == 0) {
                lin_out<1, 0>(Wo + 0 * PC * KC, s_hc, s_res, cq, bg);
                lin_out<3, 1>(Wo + 1 * PC * KC, s_hc, s_res, cq, bg);
            } else {
                lin_out<5, 4>(Wo + 2 * PC * KC, s_hc, s_res, cq, bg);
            }
        }
        __syncthreads();
    }

    // --- write out [N][9][128] ---
    {
        float4* o = (float4*)(out + (size_t)n0 * 1152);
        const float4* s = (const float4*)s_res;
        for (int idx = tid; idx < BN * 9 * 32; idx += NT) o[idx] = s[idx];
    }
}

extern "C" void kernel_launch(void* const* d_in, const int* in_sizes, int n_in,
                              void* d_out, int out_size)
{
    const float* f0 = (const float*)d_in[0];
    const float* f1 = (const float*)d_in[1];
    const float* f2 = (const float*)d_in[2];
    const float* U  = (const float*)d_in[3];
    const float* g  = (const float*)d_in[4];
    const float* Wi = (const float*)d_in[5];
    const float* Wo = (const float*)d_in[6];
    float* out = (float*)d_out;

    const int smem_bytes = SMEM_FLOATS * (int)sizeof(float);
    cudaFuncSetAttribute(cg_kernel, cudaFuncAttributeMaxDynamicSharedMemorySize, smem_bytes);
    cg_kernel<<<NN / BN, NT, smem_bytes>>>(f0, f1, f2, U, g, Wi, Wo, out);
}

// round 8
// speedup vs baseline: 1.0694x; 1.0694x over previous
#include <cuda_runtime.h>

typedef unsigned long long u64;

// ---------------- f32x2 packed-math helpers (sm_103a) ----------------
__device__ __forceinline__ u64 f2fma(u64 a, u64 b, u64 c) {
    u64 d;
    asm("fma.rn.f32x2 %0, %1, %2, %3;" : "=l"(d) : "l"(a), "l"(b), "l"(c));
    return d;
}
__device__ __forceinline__ u64 f2mul(u64 a, u64 b) {
    u64 d;
    asm("mul.rn.f32x2 %0, %1, %2;" : "=l"(d) : "l"(a), "l"(b));
    return d;
}
__device__ __forceinline__ u64 fpack(float x, float y) {
    u64 d;
    asm("mov.b64 %0, {%1, %2};" : "=l"(d) : "f"(x), "f"(y));
    return d;
}
__device__ __forceinline__ float2 funpack(u64 a) {
    float2 r;
    asm("mov.b64 {%0, %1}, %2;" : "=f"(r.x), "=f"(r.y) : "l"(a));
    return r;
}

// ---------------- problem constants ----------------
#define NN     50000
#define KC     128
#define PC     256
#define BN     8
#define NT     512
#define NI     4
#define EPSV   1e-6f

// smem layout (float offsets)
#define OFF_RES 0          // [8][9][128]  residual            9216
#define OFF_H   9216       // [8][9][128]  normed h / lin_out scratch  9216
#define OFF_HC  18432      // [8][9][256]  hc / tp             18432
#define OFF_U   36864      // [45][9] scalar sym U             405
#define OFF_G   37312      // [4][3][128]  gamma               1536
#define SMEM_FLOATS 38848

// ---------------- linear_in: h[9][K] @ Win[K][2K] -> hc[9][2K] ----------------
// Thread = (pg 0..63) x (node b 0..7); owns 4 p-cols: pg + 64j.
// k-parity f32x2 accumulators; h float4 broadcast feeds 8 f2fma (4 cols).
template<int ML, int M0>
__device__ __forceinline__ void lin_in(const float* __restrict__ W,
                                       const float* __restrict__ s_h,
                                       float* __restrict__ s_hc,
                                       int pg, int b)
{
    u64 acc[4][ML];
    #pragma unroll
    for (int j = 0; j < 4; j++)
        #pragma unroll
        for (int m = 0; m < ML; m++) acc[j][m] = 0ull;

    const float* hbase = s_h + (b * 9 + M0) * 128;

    #pragma unroll 2
    for (int k = 0; k < KC; k += 4) {
        u64 w0[4], w1[4];
        #pragma unroll
        for (int j = 0; j < 4; j++) {
            const float* wp = W + (size_t)k * PC + pg + 64 * j;
            w0[j] = fpack(wp[0],      wp[PC]);
            w1[j] = fpack(wp[2 * PC], wp[3 * PC]);
        }
        #pragma unroll
        for (int m = 0; m < ML; m++) {
            const ulonglong2 h2 = *(const ulonglong2*)(hbase + m * 128 + k);
            #pragma unroll
            for (int j = 0; j < 4; j++) {
                acc[j][m] = f2fma(h2.x, w0[j], acc[j][m]);
                acc[j][m] = f2fma(h2.y, w1[j], acc[j][m]);
            }
        }
    }
    #pragma unroll
    for (int m = 0; m < ML; m++)
        #pragma unroll
        for (int j = 0; j < 4; j++) {
            float2 v = funpack(acc[j][m]);
            s_hc[(b * 9 + M0 + m) * 256 + pg + 64 * j] = v.x + v.y;
        }
}

// ---------------- linear_out: tp[9][2K] @ Wout[2K][K] + skip, p-split ----------------
// Thread = (cq 0..31) x (node bg 0..7) x (p-half ph); owns col-pairs (cq, cq+32),
// all ML m-rows, summing over its 128-wide half of p.
// ph=1 stores partials to scratch; after a uniform sync ph=0 adds partial+skip.
template<int ML, int M0>
__device__ __forceinline__ void lin_out2(const float* __restrict__ W,
                                         const float* __restrict__ s_hc,
                                         float* __restrict__ s_res,
                                         float* __restrict__ s_scr,
                                         int cq, int bg, int ph)
{
    u64 acc0[ML], acc1[ML];
    #pragma unroll
    for (int m = 0; m < ML; m++) { acc0[m] = 0ull; acc1[m] = 0ull; }

    const float* wA = W + 2 * cq;
    const float* wB = W + 2 * (cq + 32);
    const int pbase = ph * 128;

    #pragma unroll 2
    for (int pp = 0; pp < 128; pp += 4) {
        const int p = pbase + pp;
        u64 wA0 = *(const u64*)(wA + (size_t)(p + 0) * KC);
        u64 wA1 = *(const u64*)(wA + (size_t)(p + 1) * KC);
        u64 wA2 = *(const u64*)(wA + (size_t)(p + 2) * KC);
        u64 wA3 = *(const u64*)(wA + (size_t)(p + 3) * KC);
        u64 wB0 = *(const u64*)(wB + (size_t)(p + 0) * KC);
        u64 wB1 = *(const u64*)(wB + (size_t)(p + 1) * KC);
        u64 wB2 = *(const u64*)(wB + (size_t)(p + 2) * KC);
        u64 wB3 = *(const u64*)(wB + (size_t)(p + 3) * KC);
        #pragma unroll
        for (int m = 0; m < ML; m++) {
            const float4 hv = *(const float4*)
                (s_hc + (bg * 9 + M0 + m) * 256 + p);
            u64 hx = fpack(hv.x, hv.x);
            u64 hy = fpack(hv.y, hv.y);
            u64 hz = fpack(hv.z, hv.z);
            u64 hw = fpack(hv.w, hv.w);
            acc0[m] = f2fma(hx, wA0, acc0[m]);
            acc0[m] = f2fma(hy, wA1, acc0[m]);
            acc0[m] = f2fma(hz, wA2, acc0[m]);
            acc0[m] = f2fma(hw, wA3, acc0[m]);
            acc1[m] = f2fma(hx, wB0, acc1[m]);
            acc1[m] = f2fma(hy, wB1, acc1[m]);
            acc1[m] = f2fma(hz, wB2, acc1[m]);
            acc1[m] = f2fma(hw, wB3, acc1[m]);
        }
    }

    if (ph == 1) {
        #pragma unroll
        for (int m = 0; m < ML; m++) {
            float* s0 = s_scr + (bg * 9 + M0 + m) * 128 + 2 * cq;
            *(u64*)(s0)      = acc0[m];
            *(u64*)(s0 + 64) = acc1[m];
        }
    }
    __syncthreads();   // uniform: all 512 threads call this template for every l
    if (ph == 0) {
        #pragma unroll
        for (int m = 0; m < ML; m++) {
            float* r0 = s_res + (bg * 9 + M0 + m) * 128 + 2 * cq;
            float* r1 = r0 + 64;
            const float* s0 = s_scr + (bg * 9 + M0 + m) * 128 + 2 * cq;
            float2 a  = funpack(acc0[m]);
            float2 b2 = funpack(acc1[m]);
            float2 q0 = *(const float2*)(s0);
            float2 q1 = *(const float2*)(s0 + 64);
            float2 v0 = *(float2*)r0;
            float2 v1 = *(float2*)r1;
            v0.x += a.x + q0.x;   v0.y += a.y + q0.y;
            v1.x += b2.x + q1.x;  v1.y += b2.y + q1.y;
            *(float2*)r0 = v0;
            *(float2*)r1 = v1;
        }
    }
}

// ---------------- fused 4-iteration kernel, 8 nodes per CTA, 512 threads ----------------
__global__ void __launch_bounds__(NT, 1)
cg_kernel(const float* __restrict__ f0, const float* __restrict__ f1,
          const float* __restrict__ f2, const float* __restrict__ U,
          const float* __restrict__ gamma, const float* __restrict__ Win,
          const float* __restrict__ Wout, float* __restrict__ out)
{
    extern __shared__ float sm[];
    float* s_res = sm + OFF_RES;
    float* s_h   = sm + OFF_H;
    float* s_hc  = sm + OFF_HC;
    float* s_U   = sm + OFF_U;
    float* s_g   = sm + OFF_G;

    const int tid = threadIdx.x;
    const int n0  = blockIdx.x * BN;

    // --- load features: s_res[b][m][k], m packed [f0 | f1(3) | f2(5)] ---
    {
        float4* dst = (float4*)s_res;
        for (int idx = tid; idx < BN * 9 * 32; idx += NT) {
            int b   = idx / 288;
            int rem = idx - b * 288;
            int m   = rem >> 5;
            int q   = rem & 31;
            int n   = n0 + b;
            const float* src;
            if (m == 0)      src = f0 + (size_t)n * 128;
            else if (m < 4)  src = f1 + (size_t)n * 384 + (m - 1) * 128;
            else             src = f2 + (size_t)n * 640 + (m - 4) * 128;
            dst[idx] = ((const float4*)src)[q];
        }
    }
    // --- symmetrize U into scalar pair layout s_U[pair][c] ---
    for (int tt = tid; tt < 45 * 9; tt += NT) {
        int pair = tt / 9, c = tt - pair * 9;
        int a = 0, rem = pair;
        while (rem > 8 - a) { rem -= 9 - a; a++; }
        int bb = a + rem;
        float u = U[(a * 9 + bb) * 9 + c];
        if (a != bb) u += U[(bb * 9 + a) * 9 + c];
        s_U[pair * 9 + c] = u;
    }
    for (int tt = tid; tt < NI * 3 * KC; tt += NT) s_g[tt] = gamma[tt];
    __syncthreads();

    #pragma unroll 1
    for (int it = 0; it < NI; it++) {
        // ---------- EquivariantRMSNorm -> natural h[b][m][k] ----------
        for (int idx = tid; idx < BN * KC; idx += NT) {
            int b = idx >> 7, k = idx & 127;
            const float* r = s_res + b * 1152 + k;
            float x0 = r[0];
            float x1 = r[128], x2 = r[256],  x3 = r[384];
            float x4 = r[512], x5 = r[640],  x6 = r[768], x7 = r[896], x8 = r[1024];
            float i0 = rsqrtf(x0 * x0 + EPSV);
            float i1 = rsqrtf((x1*x1 + x2*x2 + x3*x3) * (1.0f/3.0f) + EPSV);
            float i2 = rsqrtf((x4*x4 + x5*x5 + x6*x6 + x7*x7 + x8*x8) * 0.2f + EPSV);
            float g0 = s_g[(it * 3 + 0) * 128 + k];
            float g1 = s_g[(it * 3 + 1) * 128 + k];
            float g2 = s_g[(it * 3 + 2) * 128 + k];
            float* h = s_h + b * 1152 + k;
            h[0]    = x0 * i0 * g0;
            h[128]  = x1 * i1 * g1;
            h[256]  = x2 * i1 * g1;
            h[384]  = x3 * i1 * g1;
            h[512]  = x4 * i2 * g2;
            h[640]  = x5 * i2 * g2;
            h[768]  = x6 * i2 * g2;
            h[896]  = x7 * i2 * g2;
            h[1024] = x8 * i2 * g2;
        }
        __syncthreads();

        // ---------- linear_in (K -> 2K), 4 p-cols per thread ----------
        {
            const int pg = tid & 63;
            const int b  = tid >> 6;
            const float* Wi = Win + (size_t)(it * 3) * KC * PC;
            lin_in<1, 0>(Wi + 0 * KC * PC, s_h, s_hc, pg, b);
            lin_in<3, 1>(Wi + 1 * KC * PC, s_h, s_hc, pg, b);
            lin_in<5, 4>(Wi + 2 * KC * PC, s_h, s_hc, pg, b);
        }
        __syncthreads();

        // ---------- CG tensor product, register-preloaded, in-place on s_hc ----------
        {
            const int p2 = tid & 127;
            const int bq = (tid >> 7) * 2;
            float* base0 = s_hc + bq * 2304 + 2 * p2;
            float* base1 = base0 + 2304;
            u64 v0[9], v1[9];
            #pragma unroll
            for (int a = 0; a < 9; a++) {
                v0[a] = *(const u64*)(base0 + a * 256);
                v1[a] = *(const u64*)(base1 + a * 256);
            }
            u64 acc0[9], acc1[9];
            #pragma unroll
            for (int c = 0; c < 9; c++) { acc0[c] = 0ull; acc1[c] = 0ull; }
            int pair = 0;
            for (int a = 0; a < 9; a++) {
                for (int bb = a; bb < 9; bb++) {
                    u64 pr0 = f2mul(v0[a], v0[bb]);
                    u64 pr1 = f2mul(v1[a], v1[bb]);
                    const float* u = s_U + pair * 9;
                    #pragma unroll
                    for (int c = 0; c < 9; c++) {
                        float us = u[c];
                        u64 uc = fpack(us, us);
                        acc0[c] = f2fma(pr0, uc, acc0[c]);
                        acc1[c] = f2fma(pr1, uc, acc1[c]);
                    }
                    pair++;
                }
            }
            #pragma unroll
            for (int c = 0; c < 9; c++) {
                *(u64*)(base0 + c * 256) = acc0[c];
                *(u64*)(base1 + c * 256) = acc1[c];
            }
        }
        __syncthreads();

        // ---------- linear_out (2K -> K) + skip, p-split halves over s_h scratch ----------
        {
            const int cq = tid & 31;
            const int bg = (tid >> 5) & 7;
            const int ph = tid >> 8;
            const float* Wo = Wout + (size_t)(it * 3) * PC * KC;
            lin_out2<1, 0>(Wo + 0 * PC * KC, s_hc, s_res, s_h, cq, bg, ph);
            lin_out2<3, 1>(Wo + 1 * PC * KC, s_hc, s_res, s_h, cq, bg, ph);
            lin_out2<5, 4>(Wo + 2 * PC * KC, s_hc, s_res, s_h, cq, bg, ph);
        }
        __syncthreads();
    }

    // --- write out [N][9][128] ---
    {
        float4* o = (float4*)(out + (size_t)n0 * 1152);
        const float4* s = (const float4*)s_res;
        for (int idx = tid; idx < BN * 9 * 32; idx += NT) o[idx] = s[idx];
    }
}

extern "C" void kernel_launch(void* const* d_in, const int* in_sizes, int n_in,
                              void* d_out, int out_size)
{
    const float* f0 = (const float*)d_in[0];
    const float* f1 = (const float*)d_in[1];
    const float* f2 = (const float*)d_in[2];
    const float* U  = (const float*)d_in[3];
    const float* g  = (const float*)d_in[4];
    const float* Wi = (const float*)d_in[5];
    const float* Wo = (const float*)d_in[6];
    float* out = (float*)d_out;

    const int smem_bytes = SMEM_FLOATS * (int)sizeof(float);
    cudaFuncSetAttribute(cg_kernel, cudaFuncAttributeMaxDynamicSharedMemorySize, smem_bytes);
    cg_kernel<<<NN / BN, NT, smem_bytes>>>(f0, f1, f2, U, g, Wi, Wo, out);
}

// round 9
// speedup vs baseline: 1.0704x; 1.0010x over previous
#include <cuda_runtime.h>

typedef unsigned long long u64;

// ---------------- f32x2 packed-math helpers (sm_103a) ----------------
__device__ __forceinline__ u64 f2fma(u64 a, u64 b, u64 c) {
    u64 d;
    asm("fma.rn.f32x2 %0, %1, %2, %3;" : "=l"(d) : "l"(a), "l"(b), "l"(c));
    return d;
}
__device__ __forceinline__ u64 f2mul(u64 a, u64 b) {
    u64 d;
    asm("mul.rn.f32x2 %0, %1, %2;" : "=l"(d) : "l"(a), "l"(b));
    return d;
}
__device__ __forceinline__ u64 fpack(float x, float y) {
    u64 d;
    asm("mov.b64 %0, {%1, %2};" : "=l"(d) : "f"(x), "f"(y));
    return d;
}
__device__ __forceinline__ float2 funpack(u64 a) {
    float2 r;
    asm("mov.b64 {%0, %1}, %2;" : "=f"(r.x), "=f"(r.y) : "l"(a));
    return r;
}

// ---------------- problem constants ----------------
#define NN     50000
#define KC     128
#define PC     256
#define BN     8
#define NT     512
#define NI     4
#define EPSV   1e-6f

// smem layout (float offsets)
#define OFF_RES 0          // [8][9][128]  residual            9216
#define OFF_H   9216       // [8][9][128]  normed h / lin_out scratch  9216
#define OFF_HC  18432      // [8][9][256]  hc / tp             18432
#define OFF_U   36864      // [45][9] scalar sym U             405
#define OFF_G   37312      // [4][3][128]  gamma               1536
#define SMEM_FLOATS 38848

// ---------------- linear_in: h[9][K] @ Win[K][2K] -> hc[9][2K] ----------------
// Thread = (pg 0..63) x (node b 0..7); owns 4 p-cols: pg + 64j.
// k-parity f32x2 accumulators; h float4 broadcast feeds 8 f2fma (4 cols).
template<int ML, int M0>
__device__ __forceinline__ void lin_in(const float* __restrict__ W,
                                       const float* __restrict__ s_h,
                                       float* __restrict__ s_hc,
                                       int pg, int b)
{
    u64 acc[4][ML];
    #pragma unroll
    for (int j = 0; j < 4; j++)
        #pragma unroll
        for (int m = 0; m < ML; m++) acc[j][m] = 0ull;

    const float* hbase = s_h + (b * 9 + M0) * 128;

    #pragma unroll 2
    for (int k = 0; k < KC; k += 4) {
        u64 w0[4], w1[4];
        #pragma unroll
        for (int j = 0; j < 4; j++) {
            const float* wp = W + (size_t)k * PC + pg + 64 * j;
            w0[j] = fpack(wp[0],      wp[PC]);
            w1[j] = fpack(wp[2 * PC], wp[3 * PC]);
        }
        #pragma unroll
        for (int m = 0; m < ML; m++) {
            const ulonglong2 h2 = *(const ulonglong2*)(hbase + m * 128 + k);
            #pragma unroll
            for (int j = 0; j < 4; j++) {
                acc[j][m] = f2fma(h2.x, w0[j], acc[j][m]);
                acc[j][m] = f2fma(h2.y, w1[j], acc[j][m]);
            }
        }
    }
    #pragma unroll
    for (int m = 0; m < ML; m++)
        #pragma unroll
        for (int j = 0; j < 4; j++) {
            float2 v = funpack(acc[j][m]);
            s_hc[(b * 9 + M0 + m) * 256 + pg + 64 * j] = v.x + v.y;
        }
}

// ---------------- linear_out: tp[9][2K] @ Wout[2K][K] + skip, p-split ----------------
// Thread = (cq 0..31) x (node bg 0..7) x (p-half ph); owns col-pairs (cq, cq+32),
// all ML m-rows, summing over its 128-wide half of p.
// ph=1 stores partials to scratch; after a uniform sync ph=0 adds partial+skip.
template<int ML, int M0>
__device__ __forceinline__ void lin_out2(const float* __restrict__ W,
                                         const float* __restrict__ s_hc,
                                         float* __restrict__ s_res,
                                         float* __restrict__ s_scr,
                                         int cq, int bg, int ph)
{
    u64 acc0[ML], acc1[ML];
    #pragma unroll
    for (int m = 0; m < ML; m++) { acc0[m] = 0ull; acc1[m] = 0ull; }

    const float* wA = W + 2 * cq;
    const float* wB = W + 2 * (cq + 32);
    const int pbase = ph * 128;

    #pragma unroll 2
    for (int pp = 0; pp < 128; pp += 4) {
        const int p = pbase + pp;
        u64 wA0 = *(const u64*)(wA + (size_t)(p + 0) * KC);
        u64 wA1 = *(const u64*)(wA + (size_t)(p + 1) * KC);
        u64 wA2 = *(const u64*)(wA + (size_t)(p + 2) * KC);
        u64 wA3 = *(const u64*)(wA + (size_t)(p + 3) * KC);
        u64 wB0 = *(const u64*)(wB + (size_t)(p + 0) * KC);
        u64 wB1 = *(const u64*)(wB + (size_t)(p + 1) * KC);
        u64 wB2 = *(const u64*)(wB + (size_t)(p + 2) * KC);
        u64 wB3 = *(const u64*)(wB + (size_t)(p + 3) * KC);
        #pragma unroll
        for (int m = 0; m < ML; m++) {
            const float4 hv = *(const float4*)
                (s_hc + (bg * 9 + M0 + m) * 256 + p);
            u64 hx = fpack(hv.x, hv.x);
            u64 hy = fpack(hv.y, hv.y);
            u64 hz = fpack(hv.z, hv.z);
            u64 hw = fpack(hv.w, hv.w);
            acc0[m] = f2fma(hx, wA0, acc0[m]);
            acc0[m] = f2fma(hy, wA1, acc0[m]);
            acc0[m] = f2fma(hz, wA2, acc0[m]);
            acc0[m] = f2fma(hw, wA3, acc0[m]);
            acc1[m] = f2fma(hx, wB0, acc1[m]);
            acc1[m] = f2fma(hy, wB1, acc1[m]);
            acc1[m] = f2fma(hz, wB2, acc1[m]);
            acc1[m] = f2fma(hw, wB3, acc1[m]);
        }
    }

    if (ph == 1) {
        #pragma unroll
        for (int m = 0; m < ML; m++) {
            float* s0 = s_scr + (bg * 9 + M0 + m) * 128 + 2 * cq;
            *(u64*)(s0)      = acc0[m];
            *(u64*)(s0 + 64) = acc1[m];
        }
    }
    __syncthreads();   // uniform: all 512 threads call this template for every l
    if (ph == 0) {
        #pragma unroll
        for (int m = 0; m < ML; m++) {
            float* r0 = s_res + (bg * 9 + M0 + m) * 128 + 2 * cq;
            float* r1 = r0 + 64;
            const float* s0 = s_scr + (bg * 9 + M0 + m) * 128 + 2 * cq;
            float2 a  = funpack(acc0[m]);
            float2 b2 = funpack(acc1[m]);
            float2 q0 = *(const float2*)(s0);
            float2 q1 = *(const float2*)(s0 + 64);
            float2 v0 = *(float2*)r0;
            float2 v1 = *(float2*)r1;
            v0.x += a.x + q0.x;   v0.y += a.y + q0.y;
            v1.x += b2.x + q1.x;  v1.y += b2.y + q1.y;
            *(float2*)r0 = v0;
            *(float2*)r1 = v1;
        }
    }
}

// ---------------- fused 4-iteration kernel, 8 nodes per CTA, 512 threads ----------------
__global__ void __launch_bounds__(NT, 1)
cg_kernel(const float* __restrict__ f0, const float* __restrict__ f1,
          const float* __restrict__ f2, const float* __restrict__ U,
          const float* __restrict__ gamma, const float* __restrict__ Win,
          const float* __restrict__ Wout, float* __restrict__ out)
{
    extern __shared__ float sm[];
    float* s_res = sm + OFF_RES;
    float* s_h   = sm + OFF_H;
    float* s_hc  = sm + OFF_HC;
    float* s_U   = sm + OFF_U;
    float* s_g   = sm + OFF_G;

    const int tid = threadIdx.x;
    const int n0  = blockIdx.x * BN;

    // --- load features: s_res[b][m][k], m packed [f0 | f1(3) | f2(5)] ---
    {
        float4* dst = (float4*)s_res;
        for (int idx = tid; idx < BN * 9 * 32; idx += NT) {
            int b   = idx / 288;
            int rem = idx - b * 288;
            int m   = rem >> 5;
            int q   = rem & 31;
            int n   = n0 + b;
            const float* src;
            if (m == 0)      src = f0 + (size_t)n * 128;
            else if (m < 4)  src = f1 + (size_t)n * 384 + (m - 1) * 128;
            else             src = f2 + (size_t)n * 640 + (m - 4) * 128;
            dst[idx] = ((const float4*)src)[q];
        }
    }
    // --- symmetrize U into scalar pair layout s_U[pair][c] ---
    for (int tt = tid; tt < 45 * 9; tt += NT) {
        int pair = tt / 9, c = tt - pair * 9;
        int a = 0, rem = pair;
        while (rem > 8 - a) { rem -= 9 - a; a++; }
        int bb = a + rem;
        float u = U[(a * 9 + bb) * 9 + c];
        if (a != bb) u += U[(bb * 9 + a) * 9 + c];
        s_U[pair * 9 + c] = u;
    }
    for (int tt = tid; tt < NI * 3 * KC; tt += NT) s_g[tt] = gamma[tt];
    __syncthreads();

    #pragma unroll 1
    for (int it = 0; it < NI; it++) {
        // ---------- EquivariantRMSNorm -> natural h[b][m][k] ----------
        for (int idx = tid; idx < BN * KC; idx += NT) {
            int b = idx >> 7, k = idx & 127;
            const float* r = s_res + b * 1152 + k;
            float x0 = r[0];
            float x1 = r[128], x2 = r[256],  x3 = r[384];
            float x4 = r[512], x5 = r[640],  x6 = r[768], x7 = r[896], x8 = r[1024];
            float i0 = rsqrtf(x0 * x0 + EPSV);
            float i1 = rsqrtf((x1*x1 + x2*x2 + x3*x3) * (1.0f/3.0f) + EPSV);
            float i2 = rsqrtf((x4*x4 + x5*x5 + x6*x6 + x7*x7 + x8*x8) * 0.2f + EPSV);
            float g0 = s_g[(it * 3 + 0) * 128 + k];
            float g1 = s_g[(it * 3 + 1) * 128 + k];
            float g2 = s_g[(it * 3 + 2) * 128 + k];
            float* h = s_h + b * 1152 + k;
            h[0]    = x0 * i0 * g0;
            h[128]  = x1 * i1 * g1;
            h[256]  = x2 * i1 * g1;
            h[384]  = x3 * i1 * g1;
            h[512]  = x4 * i2 * g2;
            h[640]  = x5 * i2 * g2;
            h[768]  = x6 * i2 * g2;
            h[896]  = x7 * i2 * g2;
            h[1024] = x8 * i2 * g2;
        }
        __syncthreads();

        // ---------- linear_in (K -> 2K), 4 p-cols per thread ----------
        {
            const int pg = tid & 63;
            const int b  = tid >> 6;
            const float* Wi = Win + (size_t)(it * 3) * KC * PC;
            lin_in<1, 0>(Wi + 0 * KC * PC, s_h, s_hc, pg, b);
            lin_in<3, 1>(Wi + 1 * KC * PC, s_h, s_hc, pg, b);
            lin_in<5, 4>(Wi + 2 * KC * PC, s_h, s_hc, pg, b);
        }
        __syncthreads();

        // ---------- CG tensor product, register-preloaded, in-place on s_hc ----------
        {
            const int p2 = tid & 127;
            const int bq = (tid >> 7) * 2;
            float* base0 = s_hc + bq * 2304 + 2 * p2;
            float* base1 = base0 + 2304;
            u64 v0[9], v1[9];
            #pragma unroll
            for (int a = 0; a < 9; a++) {
                v0[a] = *(const u64*)(base0 + a * 256);
                v1[a] = *(const u64*)(base1 + a * 256);
            }
            u64 acc0[9], acc1[9];
            #pragma unroll
            for (int c = 0; c < 9; c++) { acc0[c] = 0ull; acc1[c] = 0ull; }
            int pair = 0;
            for (int a = 0; a < 9; a++) {
                for (int bb = a; bb < 9; bb++) {
                    u64 pr0 = f2mul(v0[a], v0[bb]);
                    u64 pr1 = f2mul(v1[a], v1[bb]);
                    const float* u = s_U + pair * 9;
                    #pragma unroll
                    for (int c = 0; c < 9; c++) {
                        float us = u[c];
                        u64 uc = fpack(us, us);
                        acc0[c] = f2fma(pr0, uc, acc0[c]);
                        acc1[c] = f2fma(pr1, uc, acc1[c]);
                    }
                    pair++;
                }
            }
            #pragma unroll
            for (int c = 0; c < 9; c++) {
                *(u64*)(base0 + c * 256) = acc0[c];
                *(u64*)(base1 + c * 256) = acc1[c];
            }
        }
        __syncthreads();

        // ---------- linear_out (2K -> K) + skip, p-split halves over s_h scratch ----------
        {
            const int cq = tid & 31;
            const int bg = (tid >> 5) & 7;
            const int ph = tid >> 8;
            const float* Wo = Wout + (size_t)(it * 3) * PC * KC;
            lin_out2<1, 0>(Wo + 0 * PC * KC, s_hc, s_res, s_h, cq, bg, ph);
            lin_out2<3, 1>(Wo + 1 * PC * KC, s_hc, s_res, s_h, cq, bg, ph);
            lin_out2<5, 4>(Wo + 2 * PC * KC, s_hc, s_res, s_h, cq, bg, ph);
        }
        __syncthreads();
    }

    // --- write out [N][9][128] ---
    {
        float4* o = (float4*)(out + (size_t)n0 * 1152);
        const float4* s = (const float4*)s_res;
        for (int idx = tid; idx < BN * 9 * 32; idx += NT) o[idx] = s[idx];
    }
}

extern "C" void kernel_launch(void* const* d_in, const int* in_sizes, int n_in,
                              void* d_out, int out_size)
{
    const float* f0 = (const float*)d_in[0];
    const float* f1 = (const float*)d_in[1];
    const float* f2 = (const float*)d_in[2];
    const float* U  = (const float*)d_in[3];
    const float* g  = (const float*)d_in[4];
    const float* Wi = (const float*)d_in[5];
    const float* Wo = (const float*)d_in[6];
    float* out = (float*)d_out;

    const int smem_bytes = SMEM_FLOATS * (int)sizeof(float);
    cudaFuncSetAttribute(cg_kernel, cudaFuncAttributeMaxDynamicSharedMemorySize, smem_bytes);
    cg_kernel<<<NN / BN, NT, smem_bytes>>>(f0, f1, f2, U, g, Wi, Wo, out);
}